// round 1
// baseline (speedup 1.0000x reference)
#include <cuda_runtime.h>
#include <cuda_bf16.h>

// ---------------------------------------------------------------------------
// GCN layer: out = relu( A_coo @ ((x .* mask) @ W) )
//   x, mask: [100000, 256] f32   W: [256, 128] f32
//   edges:   row/col int32 [1.6M], weight f32 [1.6M]
//   out:     [100000, 128] f32
//
// Pipeline (all on default stream, graph-capturable, no allocations):
//   1. zero counts
//   2. histogram edge rows      (int atomics)
//   3. GEMM h = (x.*mask)@W     (fp32, packed fma.rn.f32x2)
//   4. single-block scan -> CSR offsets (+cursor copy)
//   5. scatter edges into CSR order (int atomics on cursor)
//   6. per-row warp aggregation + relu (float4 gathers, L2 resident h)
// ---------------------------------------------------------------------------

#define NMAX 100000
#define EMAX 1600000
#define D_IN 256
#define D_OUT 128

__device__ float g_h[(size_t)NMAX * D_OUT];
__device__ int   g_counts[NMAX + 1];
__device__ int   g_offsets[NMAX + 1];
__device__ int   g_cursor[NMAX];
__device__ int   g_csr_col[EMAX];
__device__ float g_csr_w[EMAX];

// ---------------- packed f32x2 helpers ----------------
__device__ __forceinline__ unsigned long long pack2(float x, float y) {
    unsigned long long r;
    asm("mov.b64 %0, {%1, %2};" : "=l"(r) : "f"(x), "f"(y));
    return r;
}
__device__ __forceinline__ unsigned long long splat2(float x) {
    unsigned long long r;
    asm("mov.b64 %0, {%1, %1};" : "=l"(r) : "f"(x));
    return r;
}
__device__ __forceinline__ void unpack2(unsigned long long v, float& x, float& y) {
    asm("mov.b64 {%0, %1}, %2;" : "=f"(x), "=f"(y) : "l"(v));
}
__device__ __forceinline__ void ffma2(unsigned long long& d,
                                      unsigned long long a,
                                      unsigned long long b) {
    asm("fma.rn.f32x2 %0, %1, %2, %0;" : "+l"(d) : "l"(a), "l"(b));
}

// ---------------- GEMM: h[M,128] = (x .* mask)[M,256] @ W[256,128] ----------
// Block tile 128x128, K-tile 16, 256 threads, 8x8 outputs per thread.
// Accumulators are f32x2 pairs along M (pairs free from transposed-A loads).
#define TM 128
#define TN 128
#define TK 16

__global__ __launch_bounds__(256)
void gemm_kernel(const float* __restrict__ x, const float* __restrict__ mask,
                 const float* __restrict__ W, int M)
{
    __shared__ float As[TK][TM + 4];   // transposed: As[k][m], padded
    __shared__ float Bs[TK][TN];

    const int t   = threadIdx.x;
    const int tx  = t & 15;            // n-tile index (8 cols)
    const int ty  = t >> 4;            // m-tile index (8 rows)
    const int row0 = blockIdx.x * TM;

    unsigned long long acc[4][8];
#pragma unroll
    for (int i = 0; i < 4; i++)
#pragma unroll
        for (int j = 0; j < 8; j++) acc[i][j] = 0ull;

    for (int k0 = 0; k0 < D_IN; k0 += TK) {
        // --- load A tile (apply dropout mask), store transposed ---
#pragma unroll
        for (int it = 0; it < 2; it++) {
            int f  = t + it * 256;          // 0..511 float4 slots
            int r  = f >> 2;                // 0..127 row in tile
            int kq = f & 3;                 // float4 group within 16-k tile
            int gr = row0 + r;
            if (gr >= M) gr = M - 1;        // clamp (stores are predicated)
            const float4 xv = *(const float4*)&x[(size_t)gr * D_IN + k0 + kq * 4];
            const float4 mv = *(const float4*)&mask[(size_t)gr * D_IN + k0 + kq * 4];
            As[kq * 4 + 0][r] = xv.x * mv.x;
            As[kq * 4 + 1][r] = xv.y * mv.y;
            As[kq * 4 + 2][r] = xv.z * mv.z;
            As[kq * 4 + 3][r] = xv.w * mv.w;
        }
        // --- load B tile ---
#pragma unroll
        for (int it = 0; it < 2; it++) {
            int f  = t + it * 256;          // 16 rows x 32 float4
            int kk = f >> 5;
            int nq = f & 31;
            *(float4*)&Bs[kk][nq * 4] =
                *(const float4*)&W[(size_t)(k0 + kk) * D_OUT + nq * 4];
        }
        __syncthreads();

#pragma unroll
        for (int kk = 0; kk < TK; kk++) {
            const float4 a0 = *(const float4*)&As[kk][ty * 8];
            const float4 a1 = *(const float4*)&As[kk][ty * 8 + 4];
            const float4 b0 = *(const float4*)&Bs[kk][tx * 8];
            const float4 b1 = *(const float4*)&Bs[kk][tx * 8 + 4];

            unsigned long long ap[4];
            ap[0] = pack2(a0.x, a0.y);
            ap[1] = pack2(a0.z, a0.w);
            ap[2] = pack2(a1.x, a1.y);
            ap[3] = pack2(a1.z, a1.w);

            unsigned long long bs[8];
            bs[0] = splat2(b0.x); bs[1] = splat2(b0.y);
            bs[2] = splat2(b0.z); bs[3] = splat2(b0.w);
            bs[4] = splat2(b1.x); bs[5] = splat2(b1.y);
            bs[6] = splat2(b1.z); bs[7] = splat2(b1.w);

#pragma unroll
            for (int i = 0; i < 4; i++)
#pragma unroll
                for (int j = 0; j < 8; j++)
                    ffma2(acc[i][j], ap[i], bs[j]);
        }
        __syncthreads();
    }

    // --- store: acc[i][j] holds rows (ty*8+2i, ty*8+2i+1), col tx*8+j ---
#pragma unroll
    for (int i = 0; i < 4; i++) {
        float lo[8], hi[8];
#pragma unroll
        for (int j = 0; j < 8; j++) unpack2(acc[i][j], lo[j], hi[j]);
        int m0 = row0 + ty * 8 + 2 * i;
        if (m0 < M) {
            float* p = &g_h[(size_t)m0 * D_OUT + tx * 8];
            *(float4*)p       = make_float4(lo[0], lo[1], lo[2], lo[3]);
            *(float4*)(p + 4) = make_float4(lo[4], lo[5], lo[6], lo[7]);
        }
        if (m0 + 1 < M) {
            float* p = &g_h[(size_t)(m0 + 1) * D_OUT + tx * 8];
            *(float4*)p       = make_float4(hi[0], hi[1], hi[2], hi[3]);
            *(float4*)(p + 4) = make_float4(hi[4], hi[5], hi[6], hi[7]);
        }
    }
}

// ---------------- CSR build ----------------
__global__ void zero_kernel(int n)
{
    int i = blockIdx.x * blockDim.x + threadIdx.x;
    if (i <= n) g_counts[i] = 0;
}

__global__ void hist_kernel(const int* __restrict__ erow, int E)
{
    int e = blockIdx.x * blockDim.x + threadIdx.x;
    if (e < E) atomicAdd(&g_counts[erow[e]], 1);
}

// single-block exclusive scan over counts[0..n) -> offsets[0..n]
__global__ __launch_bounds__(1024)
void scan_kernel(int n)
{
    __shared__ int sums[1024];
    const int t  = threadIdx.x;
    const int CH = (n + 1023) / 1024;
    const int beg = t * CH;
    const int end = min(beg + CH, n);

    int s = 0;
    for (int i = beg; i < end; i++) s += g_counts[i];
    sums[t] = s;
    __syncthreads();

    // inclusive block scan
    for (int off = 1; off < 1024; off <<= 1) {
        int v = (t >= off) ? sums[t - off] : 0;
        __syncthreads();
        sums[t] += v;
        __syncthreads();
    }

    int run = (t > 0) ? sums[t - 1] : 0;   // exclusive base
    for (int i = beg; i < end; i++) {
        g_offsets[i] = run;
        g_cursor[i]  = run;
        run += g_counts[i];
    }
    if (beg < n && end == n) g_offsets[n] = run;
}

__global__ void scatter_kernel(const int* __restrict__ erow,
                               const int* __restrict__ ecol,
                               const float* __restrict__ ew, int E)
{
    int e = blockIdx.x * blockDim.x + threadIdx.x;
    if (e < E) {
        int p = atomicAdd(&g_cursor[erow[e]], 1);
        g_csr_col[p] = ecol[e];
        g_csr_w[p]   = ew[e];
    }
}

// ---------------- aggregation: one warp per output row ----------------
__global__ __launch_bounds__(256)
void agg_kernel(float* __restrict__ out, int N)
{
    const int wid  = (blockIdx.x * blockDim.x + threadIdx.x) >> 5;
    const int lane = threadIdx.x & 31;
    if (wid >= N) return;

    const int beg = g_offsets[wid];
    const int end = g_offsets[wid + 1];
    const float4* __restrict__ h4 = (const float4*)g_h;

    float4 a0 = make_float4(0.f, 0.f, 0.f, 0.f);
    float4 a1 = make_float4(0.f, 0.f, 0.f, 0.f);

    int e = beg;
    for (; e + 2 <= end; e += 2) {
        const int   c0 = g_csr_col[e];
        const int   c1 = g_csr_col[e + 1];
        const float w0 = g_csr_w[e];
        const float w1 = g_csr_w[e + 1];
        const float4 v0 = h4[(size_t)c0 * 32 + lane];
        const float4 v1 = h4[(size_t)c1 * 32 + lane];
        a0.x = fmaf(w0, v0.x, a0.x); a0.y = fmaf(w0, v0.y, a0.y);
        a0.z = fmaf(w0, v0.z, a0.z); a0.w = fmaf(w0, v0.w, a0.w);
        a1.x = fmaf(w1, v1.x, a1.x); a1.y = fmaf(w1, v1.y, a1.y);
        a1.z = fmaf(w1, v1.z, a1.z); a1.w = fmaf(w1, v1.w, a1.w);
    }
    if (e < end) {
        const int   c0 = g_csr_col[e];
        const float w0 = g_csr_w[e];
        const float4 v0 = h4[(size_t)c0 * 32 + lane];
        a0.x = fmaf(w0, v0.x, a0.x); a0.y = fmaf(w0, v0.y, a0.y);
        a0.z = fmaf(w0, v0.z, a0.z); a0.w = fmaf(w0, v0.w, a0.w);
    }

    float4 r;
    r.x = fmaxf(a0.x + a1.x, 0.f);
    r.y = fmaxf(a0.y + a1.y, 0.f);
    r.z = fmaxf(a0.z + a1.z, 0.f);
    r.w = fmaxf(a0.w + a1.w, 0.f);
    ((float4*)out)[(size_t)wid * 32 + lane] = r;
}

// ---------------------------------------------------------------------------
extern "C" void kernel_launch(void* const* d_in, const int* in_sizes, int n_in,
                              void* d_out, int out_size)
{
    const float* x    = (const float*)d_in[0];
    const float* mask = (const float*)d_in[1];
    const float* W    = (const float*)d_in[2];
    const int*   erow = (const int*)d_in[3];
    const int*   ecol = (const int*)d_in[4];
    const float* ew   = (const float*)d_in[5];
    float* out = (float*)d_out;

    const int M = in_sizes[0] / D_IN;   // 100000
    const int E = in_sizes[3];          // 1600000

    // CSR build
    zero_kernel<<<(M + 256) / 256, 256>>>(M);
    hist_kernel<<<(E + 255) / 256, 256>>>(erow, E);

    // dense projection (independent of CSR build; same stream serializes)
    gemm_kernel<<<(M + TM - 1) / TM, 256>>>(x, mask, W, M);

    scan_kernel<<<1, 1024>>>(M);
    scatter_kernel<<<(E + 255) / 256, 256>>>(erow, ecol, ew, E);

    // aggregation + relu
    agg_kernel<<<((size_t)M * 32 + 255) / 256, 256>>>(out, M);
}

// round 2
// speedup vs baseline: 1.4699x; 1.4699x over previous
#include <cuda_runtime.h>
#include <cuda_bf16.h>

// ---------------------------------------------------------------------------
// GCN layer: out = relu( A_coo @ ((x .* mask) @ W) )
// Pipeline: zero -> hist -> GEMM -> scan1/scan2/scan3 (hierarchical) ->
//           scatter -> per-row warp aggregation + relu
// ---------------------------------------------------------------------------

#define NMAX 100000
#define EMAX 1600000
#define D_IN 256
#define D_OUT 128
#define SCAN_B 1024
#define NBLK_MAX 128   // ceil(NMAX/1024) = 98

__device__ float g_h[(size_t)NMAX * D_OUT];
__device__ int   g_counts[NMAX + 1];
__device__ int   g_offsets[NMAX + 1];
__device__ int   g_cursor[NMAX];
__device__ int   g_csr_col[EMAX];
__device__ float g_csr_w[EMAX];
__device__ int   g_blocksums[NBLK_MAX];
__device__ int   g_blockbase[NBLK_MAX];

// ---------------- packed f32x2 helpers ----------------
__device__ __forceinline__ unsigned long long pack2(float x, float y) {
    unsigned long long r;
    asm("mov.b64 %0, {%1, %2};" : "=l"(r) : "f"(x), "f"(y));
    return r;
}
__device__ __forceinline__ unsigned long long splat2(float x) {
    unsigned long long r;
    asm("mov.b64 %0, {%1, %1};" : "=l"(r) : "f"(x));
    return r;
}
__device__ __forceinline__ void unpack2(unsigned long long v, float& x, float& y) {
    asm("mov.b64 {%0, %1}, %2;" : "=f"(x), "=f"(y) : "l"(v));
}
__device__ __forceinline__ void ffma2(unsigned long long& d,
                                      unsigned long long a,
                                      unsigned long long b) {
    asm("fma.rn.f32x2 %0, %1, %2, %0;" : "+l"(d) : "l"(a), "l"(b));
}

// ---------------- GEMM: h[M,128] = (x .* mask)[M,256] @ W[256,128] ----------
#define TM 128
#define TN 128
#define TK 16

__global__ __launch_bounds__(256)
void gemm_kernel(const float* __restrict__ x, const float* __restrict__ mask,
                 const float* __restrict__ W, int M)
{
    __shared__ float As[TK][TM + 4];   // transposed: As[k][m], padded
    __shared__ float Bs[TK][TN];

    const int t   = threadIdx.x;
    const int tx  = t & 15;            // n-tile index (8 cols)
    const int ty  = t >> 4;            // m-tile index (8 rows)
    const int row0 = blockIdx.x * TM;

    unsigned long long acc[4][8];
#pragma unroll
    for (int i = 0; i < 4; i++)
#pragma unroll
        for (int j = 0; j < 8; j++) acc[i][j] = 0ull;

    for (int k0 = 0; k0 < D_IN; k0 += TK) {
#pragma unroll
        for (int it = 0; it < 2; it++) {
            int f  = t + it * 256;          // 0..511 float4 slots
            int r  = f >> 2;                // 0..127 row in tile
            int kq = f & 3;                 // float4 group within 16-k tile
            int gr = row0 + r;
            if (gr >= M) gr = M - 1;
            const float4 xv = *(const float4*)&x[(size_t)gr * D_IN + k0 + kq * 4];
            const float4 mv = *(const float4*)&mask[(size_t)gr * D_IN + k0 + kq * 4];
            As[kq * 4 + 0][r] = xv.x * mv.x;
            As[kq * 4 + 1][r] = xv.y * mv.y;
            As[kq * 4 + 2][r] = xv.z * mv.z;
            As[kq * 4 + 3][r] = xv.w * mv.w;
        }
#pragma unroll
        for (int it = 0; it < 2; it++) {
            int f  = t + it * 256;          // 16 rows x 32 float4
            int kk = f >> 5;
            int nq = f & 31;
            *(float4*)&Bs[kk][nq * 4] =
                *(const float4*)&W[(size_t)(k0 + kk) * D_OUT + nq * 4];
        }
        __syncthreads();

#pragma unroll
        for (int kk = 0; kk < TK; kk++) {
            const float4 a0 = *(const float4*)&As[kk][ty * 8];
            const float4 a1 = *(const float4*)&As[kk][ty * 8 + 4];
            const float4 b0 = *(const float4*)&Bs[kk][tx * 8];
            const float4 b1 = *(const float4*)&Bs[kk][tx * 8 + 4];

            unsigned long long ap[4];
            ap[0] = pack2(a0.x, a0.y);
            ap[1] = pack2(a0.z, a0.w);
            ap[2] = pack2(a1.x, a1.y);
            ap[3] = pack2(a1.z, a1.w);

            unsigned long long bs[8];
            bs[0] = splat2(b0.x); bs[1] = splat2(b0.y);
            bs[2] = splat2(b0.z); bs[3] = splat2(b0.w);
            bs[4] = splat2(b1.x); bs[5] = splat2(b1.y);
            bs[6] = splat2(b1.z); bs[7] = splat2(b1.w);

#pragma unroll
            for (int i = 0; i < 4; i++)
#pragma unroll
                for (int j = 0; j < 8; j++)
                    ffma2(acc[i][j], ap[i], bs[j]);
        }
        __syncthreads();
    }

#pragma unroll
    for (int i = 0; i < 4; i++) {
        float lo[8], hi[8];
#pragma unroll
        for (int j = 0; j < 8; j++) unpack2(acc[i][j], lo[j], hi[j]);
        int m0 = row0 + ty * 8 + 2 * i;
        if (m0 < M) {
            float* p = &g_h[(size_t)m0 * D_OUT + tx * 8];
            *(float4*)p       = make_float4(lo[0], lo[1], lo[2], lo[3]);
            *(float4*)(p + 4) = make_float4(lo[4], lo[5], lo[6], lo[7]);
        }
        if (m0 + 1 < M) {
            float* p = &g_h[(size_t)(m0 + 1) * D_OUT + tx * 8];
            *(float4*)p       = make_float4(hi[0], hi[1], hi[2], hi[3]);
            *(float4*)(p + 4) = make_float4(hi[4], hi[5], hi[6], hi[7]);
        }
    }
}

// ---------------- CSR build ----------------
__global__ void zero_kernel(int n)
{
    int i = blockIdx.x * blockDim.x + threadIdx.x;
    if (i <= n) g_counts[i] = 0;
}

__global__ void hist_kernel(const int* __restrict__ erow, int E)
{
    int e = blockIdx.x * blockDim.x + threadIdx.x;
    if (e < E) atomicAdd(&g_counts[erow[e]], 1);
}

// --------- hierarchical scan: 3 cheap full-width kernels ----------
__device__ __forceinline__ int block_scan_incl(int v)
{
    __shared__ int ws[32];
    const int lane = threadIdx.x & 31;
    const int w    = threadIdx.x >> 5;
#pragma unroll
    for (int o = 1; o < 32; o <<= 1) {
        int u = __shfl_up_sync(0xFFFFFFFFu, v, o);
        if (lane >= o) v += u;
    }
    if (lane == 31) ws[w] = v;
    __syncthreads();
    if (w == 0) {
        int s = ws[lane];
#pragma unroll
        for (int o = 1; o < 32; o <<= 1) {
            int u = __shfl_up_sync(0xFFFFFFFFu, s, o);
            if (lane >= o) s += u;
        }
        ws[lane] = s;
    }
    __syncthreads();
    return v + ((w > 0) ? ws[w - 1] : 0);
}

__global__ __launch_bounds__(SCAN_B)
void scan1_kernel(int n)
{
    const int i = blockIdx.x * SCAN_B + threadIdx.x;
    const int v = (i < n) ? g_counts[i] : 0;
    const int incl = block_scan_incl(v);
    if (i < n) g_offsets[i] = incl - v;              // local exclusive
    if (threadIdx.x == SCAN_B - 1) g_blocksums[blockIdx.x] = incl;
}

__global__ __launch_bounds__(128)
void scan2_kernel(int nb, int n)
{
    const int t = threadIdx.x;
    int v = (t < nb) ? g_blocksums[t] : 0;
    const int lane = t & 31;
    const int w    = t >> 5;
    __shared__ int ws[4];
#pragma unroll
    for (int o = 1; o < 32; o <<= 1) {
        int u = __shfl_up_sync(0xFFFFFFFFu, v, o);
        if (lane >= o) v += u;
    }
    if (lane == 31) ws[w] = v;
    __syncthreads();
    int base = 0;
#pragma unroll
    for (int k = 0; k < 4; k++) if (k < w) base += ws[k];
    const int incl = v + base;
    const int vv   = (t < nb) ? g_blocksums[t] : 0;
    if (t < nb) g_blockbase[t] = incl - vv;          // exclusive base per block
    if (t == nb - 1) g_offsets[n] = incl;            // total edge count
}

__global__ __launch_bounds__(SCAN_B)
void scan3_kernel(int n)
{
    const int i = blockIdx.x * SCAN_B + threadIdx.x;
    if (i < n) {
        const int o = g_offsets[i] + g_blockbase[blockIdx.x];
        g_offsets[i] = o;
        g_cursor[i]  = o;
    }
}

__global__ void scatter_kernel(const int* __restrict__ erow,
                               const int* __restrict__ ecol,
                               const float* __restrict__ ew, int E)
{
    int e = blockIdx.x * blockDim.x + threadIdx.x;
    if (e < E) {
        int p = atomicAdd(&g_cursor[erow[e]], 1);
        g_csr_col[p] = ecol[e];
        g_csr_w[p]   = ew[e];
    }
}

// ---------------- aggregation: one warp per output row ----------------
__global__ __launch_bounds__(256)
void agg_kernel(float* __restrict__ out, int N)
{
    const int wid  = (blockIdx.x * blockDim.x + threadIdx.x) >> 5;
    const int lane = threadIdx.x & 31;
    if (wid >= N) return;

    const int beg = g_offsets[wid];
    const int end = g_offsets[wid + 1];
    const float4* __restrict__ h4 = (const float4*)g_h;

    float4 a0 = make_float4(0.f, 0.f, 0.f, 0.f);
    float4 a1 = make_float4(0.f, 0.f, 0.f, 0.f);

    int e = beg;
    for (; e + 2 <= end; e += 2) {
        const int   c0 = g_csr_col[e];
        const int   c1 = g_csr_col[e + 1];
        const float w0 = g_csr_w[e];
        const float w1 = g_csr_w[e + 1];
        const float4 v0 = h4[(size_t)c0 * 32 + lane];
        const float4 v1 = h4[(size_t)c1 * 32 + lane];
        a0.x = fmaf(w0, v0.x, a0.x); a0.y = fmaf(w0, v0.y, a0.y);
        a0.z = fmaf(w0, v0.z, a0.z); a0.w = fmaf(w0, v0.w, a0.w);
        a1.x = fmaf(w1, v1.x, a1.x); a1.y = fmaf(w1, v1.y, a1.y);
        a1.z = fmaf(w1, v1.z, a1.z); a1.w = fmaf(w1, v1.w, a1.w);
    }
    if (e < end) {
        const int   c0 = g_csr_col[e];
        const float w0 = g_csr_w[e];
        const float4 v0 = h4[(size_t)c0 * 32 + lane];
        a0.x = fmaf(w0, v0.x, a0.x); a0.y = fmaf(w0, v0.y, a0.y);
        a0.z = fmaf(w0, v0.z, a0.z); a0.w = fmaf(w0, v0.w, a0.w);
    }

    float4 r;
    r.x = fmaxf(a0.x + a1.x, 0.f);
    r.y = fmaxf(a0.y + a1.y, 0.f);
    r.z = fmaxf(a0.z + a1.z, 0.f);
    r.w = fmaxf(a0.w + a1.w, 0.f);
    ((float4*)out)[(size_t)wid * 32 + lane] = r;
}

// ---------------------------------------------------------------------------
extern "C" void kernel_launch(void* const* d_in, const int* in_sizes, int n_in,
                              void* d_out, int out_size)
{
    const float* x    = (const float*)d_in[0];
    const float* mask = (const float*)d_in[1];
    const float* W    = (const float*)d_in[2];
    const int*   erow = (const int*)d_in[3];
    const int*   ecol = (const int*)d_in[4];
    const float* ew   = (const float*)d_in[5];
    float* out = (float*)d_out;

    const int M = in_sizes[0] / D_IN;   // 100000
    const int E = in_sizes[3];          // 1600000
    const int nblk = (M + SCAN_B - 1) / SCAN_B;   // 98

    zero_kernel<<<(M + 256) / 256, 256>>>(M);
    hist_kernel<<<(E + 255) / 256, 256>>>(erow, E);

    gemm_kernel<<<(M + TM - 1) / TM, 256>>>(x, mask, W, M);

    scan1_kernel<<<nblk, SCAN_B>>>(M);
    scan2_kernel<<<1, 128>>>(nblk, M);
    scan3_kernel<<<nblk, SCAN_B>>>(M);

    scatter_kernel<<<(E + 255) / 256, 256>>>(erow, ecol, ew, E);

    agg_kernel<<<((size_t)M * 32 + 255) / 256, 256>>>(out, M);
}

// round 3
// speedup vs baseline: 1.5948x; 1.0850x over previous
#include <cuda_runtime.h>
#include <cuda_bf16.h>

// ---------------------------------------------------------------------------
// GCN layer: out = relu( A_coo @ ((x .* mask) @ W) )
// Graph-parallel pipeline (fork/join captured into the CUDA graph):
//   main stream : zero -> hist -> scan1/2/3 -> scatter ----\
//   side stream : gemm  ------------------------------------+--> agg (+relu)
// ---------------------------------------------------------------------------

#define NMAX 100000
#define EMAX 1600000
#define D_IN 256
#define D_OUT 128
#define SCAN_B 1024
#define NBLK_MAX 128

__device__ float g_h[(size_t)NMAX * D_OUT];
__device__ int   g_counts[NMAX + 1];
__device__ int   g_offsets[NMAX + 1];
__device__ int   g_cursor[NMAX];
__device__ int   g_csr_col[EMAX];
__device__ float g_csr_w[EMAX];
__device__ int   g_blocksums[NBLK_MAX];
__device__ int   g_blockbase[NBLK_MAX];

// ---------------- packed f32x2 helpers ----------------
__device__ __forceinline__ unsigned long long splat2(float x) {
    unsigned long long r;
    asm("mov.b64 %0, {%1, %1};" : "=l"(r) : "f"(x));
    return r;
}
__device__ __forceinline__ void unpack2(unsigned long long v, float& x, float& y) {
    asm("mov.b64 {%0, %1}, %2;" : "=f"(x), "=f"(y) : "l"(v));
}
__device__ __forceinline__ void ffma2(unsigned long long& d,
                                      unsigned long long a,
                                      unsigned long long b) {
    asm("fma.rn.f32x2 %0, %1, %2, %0;" : "+l"(d) : "l"(a), "l"(b));
}

// ---------------- GEMM: h[M,128] = (x .* mask)[M,256] @ W[256,128] ----------
#define TM 128
#define TN 128
#define TK 16

__global__ __launch_bounds__(256)
void gemm_kernel(const float* __restrict__ x, const float* __restrict__ mask,
                 const float* __restrict__ W, int M)
{
    __shared__ float As[TK][TM + 4];   // transposed: As[k][m]; row = 528B (8B-aligned)
    __shared__ float Bs[TK][TN];

    const int t   = threadIdx.x;
    const int tx  = t & 15;            // n-octet
    const int ty  = t >> 4;            // m-octet
    const int row0 = blockIdx.x * TM;

    unsigned long long acc[4][8];
#pragma unroll
    for (int i = 0; i < 4; i++)
#pragma unroll
        for (int j = 0; j < 8; j++) acc[i][j] = 0ull;

    for (int k0 = 0; k0 < D_IN; k0 += TK) {
#pragma unroll
        for (int it = 0; it < 2; it++) {
            int f  = t + it * 256;
            int r  = f >> 2;
            int kq = f & 3;
            int gr = row0 + r;
            if (gr >= M) gr = M - 1;
            const float4 xv = *(const float4*)&x[(size_t)gr * D_IN + k0 + kq * 4];
            const float4 mv = *(const float4*)&mask[(size_t)gr * D_IN + k0 + kq * 4];
            As[kq * 4 + 0][r] = xv.x * mv.x;
            As[kq * 4 + 1][r] = xv.y * mv.y;
            As[kq * 4 + 2][r] = xv.z * mv.z;
            As[kq * 4 + 3][r] = xv.w * mv.w;
        }
#pragma unroll
        for (int it = 0; it < 2; it++) {
            int f  = t + it * 256;
            int kk = f >> 5;
            int nq = f & 31;
            *(float4*)&Bs[kk][nq * 4] =
                *(const float4*)&W[(size_t)(k0 + kk) * D_OUT + nq * 4];
        }
        __syncthreads();

#pragma unroll
        for (int kk = 0; kk < TK; kk++) {
            // A pairs: contiguous along m in transposed As -> direct 64-bit loads
            const unsigned long long* apm =
                (const unsigned long long*)&As[kk][ty * 8];
            unsigned long long ap[4];
            ap[0] = apm[0]; ap[1] = apm[1]; ap[2] = apm[2]; ap[3] = apm[3];

            const float4 b0 = *(const float4*)&Bs[kk][tx * 8];
            const float4 b1 = *(const float4*)&Bs[kk][tx * 8 + 4];
            unsigned long long bs[8];
            bs[0] = splat2(b0.x); bs[1] = splat2(b0.y);
            bs[2] = splat2(b0.z); bs[3] = splat2(b0.w);
            bs[4] = splat2(b1.x); bs[5] = splat2(b1.y);
            bs[6] = splat2(b1.z); bs[7] = splat2(b1.w);

#pragma unroll
            for (int i = 0; i < 4; i++)
#pragma unroll
                for (int j = 0; j < 8; j++)
                    ffma2(acc[i][j], ap[i], bs[j]);
        }
        __syncthreads();
    }

#pragma unroll
    for (int i = 0; i < 4; i++) {
        float lo[8], hi[8];
#pragma unroll
        for (int j = 0; j < 8; j++) unpack2(acc[i][j], lo[j], hi[j]);
        int m0 = row0 + ty * 8 + 2 * i;
        if (m0 < M) {
            float* p = &g_h[(size_t)m0 * D_OUT + tx * 8];
            *(float4*)p       = make_float4(lo[0], lo[1], lo[2], lo[3]);
            *(float4*)(p + 4) = make_float4(lo[4], lo[5], lo[6], lo[7]);
        }
        if (m0 + 1 < M) {
            float* p = &g_h[(size_t)(m0 + 1) * D_OUT + tx * 8];
            *(float4*)p       = make_float4(hi[0], hi[1], hi[2], hi[3]);
            *(float4*)(p + 4) = make_float4(hi[4], hi[5], hi[6], hi[7]);
        }
    }
}

// ---------------- CSR build ----------------
__global__ void zero_kernel(int n)
{
    int i = blockIdx.x * blockDim.x + threadIdx.x;
    if (i <= n) g_counts[i] = 0;
}

__global__ void hist_kernel(const int* __restrict__ erow, int E)
{
    int e = blockIdx.x * blockDim.x + threadIdx.x;
    if (e < E) atomicAdd(&g_counts[erow[e]], 1);
}

__device__ __forceinline__ int block_scan_incl(int v)
{
    __shared__ int ws[32];
    const int lane = threadIdx.x & 31;
    const int w    = threadIdx.x >> 5;
#pragma unroll
    for (int o = 1; o < 32; o <<= 1) {
        int u = __shfl_up_sync(0xFFFFFFFFu, v, o);
        if (lane >= o) v += u;
    }
    if (lane == 31) ws[w] = v;
    __syncthreads();
    if (w == 0) {
        int s = ws[lane];
#pragma unroll
        for (int o = 1; o < 32; o <<= 1) {
            int u = __shfl_up_sync(0xFFFFFFFFu, s, o);
            if (lane >= o) s += u;
        }
        ws[lane] = s;
    }
    __syncthreads();
    return v + ((w > 0) ? ws[w - 1] : 0);
}

__global__ __launch_bounds__(SCAN_B)
void scan1_kernel(int n)
{
    const int i = blockIdx.x * SCAN_B + threadIdx.x;
    const int v = (i < n) ? g_counts[i] : 0;
    const int incl = block_scan_incl(v);
    if (i < n) g_offsets[i] = incl - v;
    if (threadIdx.x == SCAN_B - 1) g_blocksums[blockIdx.x] = incl;
}

__global__ __launch_bounds__(128)
void scan2_kernel(int nb, int n)
{
    const int t = threadIdx.x;
    int v = (t < nb) ? g_blocksums[t] : 0;
    const int lane = t & 31;
    const int w    = t >> 5;
    __shared__ int ws[4];
#pragma unroll
    for (int o = 1; o < 32; o <<= 1) {
        int u = __shfl_up_sync(0xFFFFFFFFu, v, o);
        if (lane >= o) v += u;
    }
    if (lane == 31) ws[w] = v;
    __syncthreads();
    int base = 0;
#pragma unroll
    for (int k = 0; k < 4; k++) if (k < w) base += ws[k];
    const int incl = v + base;
    const int vv   = (t < nb) ? g_blocksums[t] : 0;
    if (t < nb) g_blockbase[t] = incl - vv;
    if (t == nb - 1) g_offsets[n] = incl;
}

__global__ __launch_bounds__(SCAN_B)
void scan3_kernel(int n)
{
    const int i = blockIdx.x * SCAN_B + threadIdx.x;
    if (i < n) {
        const int o = g_offsets[i] + g_blockbase[blockIdx.x];
        g_offsets[i] = o;
        g_cursor[i]  = o;
    }
}

__global__ void scatter_kernel(const int* __restrict__ erow,
                               const int* __restrict__ ecol,
                               const float* __restrict__ ew, int E)
{
    int e = blockIdx.x * blockDim.x + threadIdx.x;
    if (e < E) {
        int p = atomicAdd(&g_cursor[erow[e]], 1);
        g_csr_col[p] = ecol[e];
        g_csr_w[p]   = ew[e];
    }
}

// ---------------- aggregation: one warp per output row ----------------
__global__ __launch_bounds__(256)
void agg_kernel(float* __restrict__ out, int N)
{
    const int wid  = (blockIdx.x * blockDim.x + threadIdx.x) >> 5;
    const int lane = threadIdx.x & 31;
    if (wid >= N) return;

    const int beg = g_offsets[wid];
    const int end = g_offsets[wid + 1];
    const float4* __restrict__ h4 = (const float4*)g_h;

    float4 a0 = make_float4(0.f, 0.f, 0.f, 0.f);
    float4 a1 = make_float4(0.f, 0.f, 0.f, 0.f);

    int e = beg;
    for (; e + 2 <= end; e += 2) {
        const int   c0 = g_csr_col[e];
        const int   c1 = g_csr_col[e + 1];
        const float w0 = g_csr_w[e];
        const float w1 = g_csr_w[e + 1];
        const float4 v0 = h4[(size_t)c0 * 32 + lane];
        const float4 v1 = h4[(size_t)c1 * 32 + lane];
        a0.x = fmaf(w0, v0.x, a0.x); a0.y = fmaf(w0, v0.y, a0.y);
        a0.z = fmaf(w0, v0.z, a0.z); a0.w = fmaf(w0, v0.w, a0.w);
        a1.x = fmaf(w1, v1.x, a1.x); a1.y = fmaf(w1, v1.y, a1.y);
        a1.z = fmaf(w1, v1.z, a1.z); a1.w = fmaf(w1, v1.w, a1.w);
    }
    if (e < end) {
        const int   c0 = g_csr_col[e];
        const float w0 = g_csr_w[e];
        const float4 v0 = h4[(size_t)c0 * 32 + lane];
        a0.x = fmaf(w0, v0.x, a0.x); a0.y = fmaf(w0, v0.y, a0.y);
        a0.z = fmaf(w0, v0.z, a0.z); a0.w = fmaf(w0, v0.w, a0.w);
    }

    float4 r;
    r.x = fmaxf(a0.x + a1.x, 0.f);
    r.y = fmaxf(a0.y + a1.y, 0.f);
    r.z = fmaxf(a0.z + a1.z, 0.f);
    r.w = fmaxf(a0.w + a1.w, 0.f);
    ((float4*)out)[(size_t)wid * 32 + lane] = r;
}

// ---------------------------------------------------------------------------
extern "C" void kernel_launch(void* const* d_in, const int* in_sizes, int n_in,
                              void* d_out, int out_size)
{
    const float* x    = (const float*)d_in[0];
    const float* mask = (const float*)d_in[1];
    const float* W    = (const float*)d_in[2];
    const int*   erow = (const int*)d_in[3];
    const int*   ecol = (const int*)d_in[4];
    const float* ew   = (const float*)d_in[5];
    float* out = (float*)d_out;

    const int M = in_sizes[0] / D_IN;   // 100000
    const int E = in_sizes[3];          // 1600000
    const int nblk = (M + SCAN_B - 1) / SCAN_B;

    // Persistent side stream + events (host objects only; created on the
    // first — uncaptured — correctness call, reused in every capture so the
    // captured graph is identical each time).
    static cudaStream_t s_side = nullptr;
    static cudaEvent_t  s_fork = nullptr, s_join = nullptr;
    if (s_side == nullptr) {
        cudaStreamCreateWithFlags(&s_side, cudaStreamNonBlocking);
        cudaEventCreateWithFlags(&s_fork, cudaEventDisableTiming);
        cudaEventCreateWithFlags(&s_join, cudaEventDisableTiming);
    }

    // fork: side stream runs the GEMM
    cudaEventRecord(s_fork, 0);
    cudaStreamWaitEvent(s_side, s_fork, 0);
    gemm_kernel<<<(M + TM - 1) / TM, 256, 0, s_side>>>(x, mask, W, M);
    cudaEventRecord(s_join, s_side);

    // main stream: CSR build
    zero_kernel<<<(M + 256) / 256, 256>>>(M);
    hist_kernel<<<(E + 255) / 256, 256>>>(erow, E);
    scan1_kernel<<<nblk, SCAN_B>>>(M);
    scan2_kernel<<<1, 128>>>(nblk, M);
    scan3_kernel<<<nblk, SCAN_B>>>(M);
    scatter_kernel<<<(E + 255) / 256, 256>>>(erow, ecol, ew, E);

    // join, then aggregate
    cudaStreamWaitEvent(0, s_join, 0);
    agg_kernel<<<((size_t)M * 32 + 255) / 256, 256>>>(out, M);
}